// round 15
// baseline (speedup 1.0000x reference)
#include <cuda_runtime.h>
#include <cuda_bf16.h>
#include <stdint.h>

#define TM 128
#define THREADS 512
#define APAD 40
#define BPAD 40
#define HP 264

// device scratch
__device__ __align__(16) __nv_bfloat16 g_Wt[256 * 512];   // [n][k] decoder weights, bf16
__device__ __align__(16) __nv_bfloat16 g_Wp2[256 * 256];  // [p*16+c][k] head weights, bf16
__device__ float g_sums[16];
__device__ float g_cnts[16];
__device__ int g_done;

struct SmemT {
  __nv_bfloat16 As[2][128 * APAD];
  __nv_bfloat16 Bs[2][256 * BPAD];
  __nv_bfloat16 h[128 * HP];
  float Lg[128 * 17];
  float bias[256];
  float bpred[256];
  int em[16 * 24];
  int spair[128];
  int slabel[128];
  float psum[16];
  int cnt[16];
  int offp[16];
  int cur[16];
  int bucket[128];
};

__global__ void prep_kernel(const float* __restrict__ W1, const float* __restrict__ W2,
                            const float* __restrict__ Wp) {
  int i = blockIdx.x * blockDim.x + threadIdx.x;
  if (i < 256 * 512) {
    int n = i >> 9, k = i & 511;
    float v = (k < 256) ? W1[k * 256 + n] : W2[(k - 256) * 256 + n];
    g_Wt[n * 512 + k] = __float2bfloat16(v);
  }
  if (i < 256 * 256) {
    int col = i >> 8, k = i & 255;
    int p = col >> 4, c = col & 15;
    g_Wp2[col * 256 + k] = __float2bfloat16(Wp[p * 4096 + k * 16 + c]);
  }
  if (i < 16) { g_sums[i] = 0.f; g_cnts[i] = 0.f; }
  if (i == 0) g_done = 0;
}

__device__ __forceinline__ void mma16816(float* c, uint32_t a0, uint32_t a1, uint32_t a2,
                                         uint32_t a3, uint32_t b0, uint32_t b1) {
  asm volatile(
      "mma.sync.aligned.m16n8k16.row.col.f32.bf16.bf16.f32 "
      "{%0,%1,%2,%3}, {%4,%5,%6,%7}, {%8,%9}, {%0,%1,%2,%3};\n"
      : "+f"(c[0]), "+f"(c[1]), "+f"(c[2]), "+f"(c[3])
      : "r"(a0), "r"(a1), "r"(a2), "r"(a3), "r"(b0), "r"(b1));
}

__device__ __forceinline__ void ldsm4(uint32_t& r0, uint32_t& r1, uint32_t& r2, uint32_t& r3,
                                      uint32_t a) {
  asm volatile("ldmatrix.sync.aligned.m8n8.x4.shared.b16 {%0,%1,%2,%3}, [%4];"
               : "=r"(r0), "=r"(r1), "=r"(r2), "=r"(r3)
               : "r"(a));
}

__device__ __forceinline__ uint32_t s2u(const void* p) {
  uint32_t a;
  asm("{ .reg .u64 t; cvta.to.shared.u64 t, %1; cvt.u32.u64 %0, t; }" : "=r"(a) : "l"(p));
  return a;
}

__device__ __forceinline__ uint4 pack8(float4 a, float4 b) {
  __nv_bfloat162 p0 = __floats2bfloat162_rn(a.x, a.y);
  __nv_bfloat162 p1 = __floats2bfloat162_rn(a.z, a.w);
  __nv_bfloat162 p2 = __floats2bfloat162_rn(b.x, b.y);
  __nv_bfloat162 p3 = __floats2bfloat162_rn(b.z, b.w);
  uint4 u;
  u.x = *(uint32_t*)&p0; u.y = *(uint32_t*)&p1;
  u.z = *(uint32_t*)&p2; u.w = *(uint32_t*)&p3;
  return u;
}

__global__ __launch_bounds__(THREADS, 1)
void main_kernel(const float* __restrict__ h_src, const float* __restrict__ h_dst,
                 const float* __restrict__ b_dec, const float* __restrict__ b_pred,
                 const int* __restrict__ st, const int* __restrict__ dt,
                 const int* __restrict__ etc, const int* __restrict__ emap,
                 float* __restrict__ out, int E) {
  extern __shared__ __align__(16) char smem_raw[];
  SmemT* S = (SmemT*)smem_raw;
  const int tid = threadIdx.x;
  const int warp = tid >> 5, lane = tid & 31;
  const int wm = warp & 3, wn = warp >> 2;
  const long e0 = (long)blockIdx.x * TM;
  const int kq = (lane & 3) * 2;
  const int rb = lane >> 2;
  const uint32_t su = s2u(smem_raw);
  const int nvalid = (int)((E - e0) < TM ? (E - e0) : TM);
  // per-lane ldmatrix fragment offset (bytes): row (lane&15), k-half (lane&16)
  const uint32_t fro = (uint32_t)(((lane & 15) * APAD + ((lane >> 4) & 1) * 8) * 2);

  for (int i = tid; i < 256; i += THREADS) { S->bias[i] = b_dec[i]; S->bpred[i] = b_pred[i]; }
  for (int i = tid; i < 384; i += THREADS) S->em[i] = emap[i];
  if (tid < 16) { S->psum[tid] = 0.f; S->cnt[tid] = 0; }
  __syncthreads();
  if (tid < 128) {
    long e = e0 + tid; if (e >= E) e = E - 1;
    int p = st[e] * 4 + dt[e];
    S->spair[tid] = p;
    S->slabel[tid] = S->em[p * 24 + etc[e]];
    if (tid < nvalid) atomicAdd(&S->cnt[p], 1);
  }
  __syncthreads();
  if (tid == 0) {
    int a = 0;
#pragma unroll
    for (int p = 0; p < 16; ++p) { S->offp[p] = a; S->cur[p] = a; a += S->cnt[p]; }
  }
  __syncthreads();
  if (tid < nvalid) {
    int pos = atomicAdd(&S->cur[S->spair[tid]], 1);
    S->bucket[pos] = tid;
  }

  // ---- GEMM1: h = relu([h_src|h_dst] @ Wt^T + b), KC=32 double-buffered ----
  float acc[2][8][4];
#pragma unroll
  for (int a = 0; a < 2; a++)
#pragma unroll
    for (int b = 0; b < 8; b++)
#pragma unroll
      for (int c = 0; c < 4; c++) acc[a][b][c] = 0.f;

  const int ar = tid >> 2, ac = (tid & 3) * 8;
  long ae = e0 + ar; if (ae >= E) ae = E - 1;
  const int bn = tid >> 1, bh = (tid & 1) * 16;

  const float* apA = h_src + ae * 256;
  float4 av0 = *(const float4*)(apA + ac);
  float4 av1 = *(const float4*)(apA + ac + 4);
  uint4 bv0 = *(const uint4*)(g_Wt + bn * 512 + bh);
  uint4 bv1 = *(const uint4*)(g_Wt + bn * 512 + bh + 8);

  *(uint4*)(&S->As[0][ar * APAD + ac]) = pack8(av0, av1);
  *(uint4*)(&S->Bs[0][bn * BPAD + bh]) = bv0;
  *(uint4*)(&S->Bs[0][bn * BPAD + bh + 8]) = bv1;
  __syncthreads();

  const uint32_t A0u = su + (uint32_t)((char*)&S->As[0][0] - smem_raw);
  const uint32_t A1u = su + (uint32_t)((char*)&S->As[1][0] - smem_raw);
  const uint32_t B0u = su + (uint32_t)((char*)&S->Bs[0][0] - smem_raw);
  const uint32_t B1u = su + (uint32_t)((char*)&S->Bs[1][0] - smem_raw);

#pragma unroll 2
  for (int it = 0; it < 16; ++it) {
    const int cur = it & 1;
    const bool more = (it + 1 < 16);
    if (more) {
      int kb = (it + 1) * 32;
      const float* ap = (kb < 256) ? (h_src + ae * 256 + kb) : (h_dst + ae * 256 + (kb - 256));
      av0 = *(const float4*)(ap + ac);
      av1 = *(const float4*)(ap + ac + 4);
      bv0 = *(const uint4*)(g_Wt + bn * 512 + kb + bh);
      bv1 = *(const uint4*)(g_Wt + bn * 512 + kb + bh + 8);
    }
    const uint32_t Au = (cur ? A1u : A0u);
    const uint32_t Bu = (cur ? B1u : B0u);
#pragma unroll
    for (int ks = 0; ks < 2; ++ks) {
      const int kk = ks * 16;
      uint32_t af[2][4], bf[4][4];
      ldsm4(af[0][0], af[0][1], af[0][2], af[0][3],
            Au + (uint32_t)(((wm * 32) * APAD + kk) * 2) + fro);
      ldsm4(af[1][0], af[1][1], af[1][2], af[1][3],
            Au + (uint32_t)(((wm * 32 + 16) * APAD + kk) * 2) + fro);
      ldsm4(bf[0][0], bf[0][1], bf[0][2], bf[0][3],
            Bu + (uint32_t)(((wn * 64) * BPAD + kk) * 2) + fro);
      ldsm4(bf[1][0], bf[1][1], bf[1][2], bf[1][3],
            Bu + (uint32_t)(((wn * 64 + 16) * BPAD + kk) * 2) + fro);
      mma16816(acc[0][0], af[0][0], af[0][1], af[0][2], af[0][3], bf[0][0], bf[0][2]);
      mma16816(acc[1][0], af[1][0], af[1][1], af[1][2], af[1][3], bf[0][0], bf[0][2]);
      mma16816(acc[0][1], af[0][0], af[0][1], af[0][2], af[0][3], bf[0][1], bf[0][3]);
      mma16816(acc[1][1], af[1][0], af[1][1], af[1][2], af[1][3], bf[0][1], bf[0][3]);
      ldsm4(bf[2][0], bf[2][1], bf[2][2], bf[2][3],
            Bu + (uint32_t)(((wn * 64 + 32) * BPAD + kk) * 2) + fro);
      mma16816(acc[0][2], af[0][0], af[0][1], af[0][2], af[0][3], bf[1][0], bf[1][2]);
      mma16816(acc[1][2], af[1][0], af[1][1], af[1][2], af[1][3], bf[1][0], bf[1][2]);
      mma16816(acc[0][3], af[0][0], af[0][1], af[0][2], af[0][3], bf[1][1], bf[1][3]);
      mma16816(acc[1][3], af[1][0], af[1][1], af[1][2], af[1][3], bf[1][1], bf[1][3]);
      ldsm4(bf[3][0], bf[3][1], bf[3][2], bf[3][3],
            Bu + (uint32_t)(((wn * 64 + 48) * BPAD + kk) * 2) + fro);
      mma16816(acc[0][4], af[0][0], af[0][1], af[0][2], af[0][3], bf[2][0], bf[2][2]);
      mma16816(acc[1][4], af[1][0], af[1][1], af[1][2], af[1][3], bf[2][0], bf[2][2]);
      mma16816(acc[0][5], af[0][0], af[0][1], af[0][2], af[0][3], bf[2][1], bf[2][3]);
      mma16816(acc[1][5], af[1][0], af[1][1], af[1][2], af[1][3], bf[2][1], bf[2][3]);
      mma16816(acc[0][6], af[0][0], af[0][1], af[0][2], af[0][3], bf[3][0], bf[3][2]);
      mma16816(acc[1][6], af[1][0], af[1][1], af[1][2], af[1][3], bf[3][0], bf[3][2]);
      mma16816(acc[0][7], af[0][0], af[0][1], af[0][2], af[0][3], bf[3][1], bf[3][3]);
      mma16816(acc[1][7], af[1][0], af[1][1], af[1][2], af[1][3], bf[3][1], bf[3][3]);
    }
    if (more) {
      *(uint4*)(&S->As[cur ^ 1][ar * APAD + ac]) = pack8(av0, av1);
      *(uint4*)(&S->Bs[cur ^ 1][bn * BPAD + bh]) = bv0;
      *(uint4*)(&S->Bs[cur ^ 1][bn * BPAD + bh + 8]) = bv1;
    }
    __syncthreads();
  }

  // epilogue: bias + relu -> h (bf16 in smem)
  char* Hb = (char*)S->h;
#pragma unroll
  for (int mi = 0; mi < 2; ++mi) {
    int r = wm * 32 + mi * 16 + rb;
#pragma unroll
    for (int ni = 0; ni < 8; ++ni) {
      int n0 = wn * 64 + ni * 8 + (lane & 3) * 2;
      float bb0 = S->bias[n0], bb1 = S->bias[n0 + 1];
      __nv_bfloat162 q0 = __floats2bfloat162_rn(fmaxf(acc[mi][ni][0] + bb0, 0.f),
                                                fmaxf(acc[mi][ni][1] + bb1, 0.f));
      __nv_bfloat162 q1 = __floats2bfloat162_rn(fmaxf(acc[mi][ni][2] + bb0, 0.f),
                                                fmaxf(acc[mi][ni][3] + bb1, 0.f));
      *(uint32_t*)(Hb + (r * HP + n0) * 2) = *(uint32_t*)&q0;
      *(uint32_t*)(Hb + ((r + 8) * HP + n0) * 2) = *(uint32_t*)&q1;
    }
  }
  __syncthreads();

  // ---- GEMM2 (bucketed): warp w handles pair w; ldmatrix row-gather ----
  {
    const int p = warp;
    const int m = S->cnt[p];
    const int off = S->offp[p];
    const uint32_t Hu = su + (uint32_t)((char*)&S->h[0] - smem_raw);
    const __nv_bfloat16* Wb = g_Wp2 + (p * 16) * 256;  // 16 cols x 256 k, L2-hot
    for (int t = 0; t * 16 < m; ++t) {
      // per-lane gather address: lanes 0-15 -> bucketed rows @k0, 16-31 same rows @k+8
      int idx = t * 16 + (lane & 15);
      int rl = (idx < m) ? S->bucket[off + idx] : S->bucket[off];
      uint32_t abase = Hu + (uint32_t)(rl * HP * 2) + ((lane >> 4) & 1) * 16;
      float a0[4] = {0.f, 0.f, 0.f, 0.f};
      float a1[4] = {0.f, 0.f, 0.f, 0.f};
#pragma unroll 4
      for (int ks = 0; ks < 16; ++ks) {
        int kk = ks * 16 + kq;
        uint32_t f0, f1, f2, f3;
        ldsm4(f0, f1, f2, f3, abase + (uint32_t)(ks * 32));
        uint32_t b0 = *(const uint32_t*)(Wb + rb * 256 + kk);
        uint32_t b1 = *(const uint32_t*)(Wb + rb * 256 + kk + 8);
        uint32_t b2 = *(const uint32_t*)(Wb + (8 + rb) * 256 + kk);
        uint32_t b3 = *(const uint32_t*)(Wb + (8 + rb) * 256 + kk + 8);
        mma16816(a0, f0, f1, f2, f3, b0, b1);
        mma16816(a1, f0, f1, f2, f3, b2, b3);
      }
      int i0 = t * 16 + rb, i1 = i0 + 8;
      int c0 = (lane & 3) * 2;
      if (i0 < m) {
        int r0 = S->bucket[off + i0];
        S->Lg[r0 * 17 + c0] = a0[0];
        S->Lg[r0 * 17 + c0 + 1] = a0[1];
        S->Lg[r0 * 17 + 8 + c0] = a1[0];
        S->Lg[r0 * 17 + 8 + c0 + 1] = a1[1];
      }
      if (i1 < m) {
        int r1 = S->bucket[off + i1];
        S->Lg[r1 * 17 + c0] = a0[2];
        S->Lg[r1 * 17 + c0 + 1] = a0[3];
        S->Lg[r1 * 17 + 8 + c0] = a1[2];
        S->Lg[r1 * 17 + 8 + c0 + 1] = a1[3];
      }
    }
  }
  __syncthreads();

  // per-edge softmax NLL + per-pair partials
  if (tid < nvalid) {
    const float* L = S->Lg + tid * 17;
    const float* bp = S->bpred + S->spair[tid] * 16;
    float mx = -1e30f;
    float Lb[16];
#pragma unroll
    for (int c = 0; c < 16; ++c) { Lb[c] = L[c] + bp[c]; mx = fmaxf(mx, Lb[c]); }
    float s = 0.f;
#pragma unroll
    for (int c = 0; c < 16; ++c) s += __expf(Lb[c] - mx);
    float l = __logf(s) + mx - Lb[S->slabel[tid]];
    atomicAdd(&S->psum[S->spair[tid]], l);
  }
  __syncthreads();
  if (tid < 16 && S->cnt[tid] > 0) {
    atomicAdd(&g_sums[tid], S->psum[tid]);
    atomicAdd(&g_cnts[tid], (float)S->cnt[tid]);
  }
  __threadfence();
  __syncthreads();
  if (tid == 0) {
    int prev = atomicAdd(&g_done, 1);
    if (prev == (int)gridDim.x - 1) {
      __threadfence();
      float ls = 0.f, np = 0.f;
#pragma unroll
      for (int p = 0; p < 16; ++p) {
        float c = g_cnts[p];
        if (c > 0.f) { ls += g_sums[p] / c; np += 1.f; }
      }
      out[0] = ls / np;
    }
  }
}

extern "C" void kernel_launch(void* const* d_in, const int* in_sizes, int n_in,
                              void* d_out, int out_size) {
  const float* h_src = (const float*)d_in[0];
  const float* h_dst = (const float*)d_in[1];
  const float* W1 = (const float*)d_in[2];
  const float* W2 = (const float*)d_in[3];
  const float* b_dec = (const float*)d_in[4];
  const float* W_pred = (const float*)d_in[5];
  const float* b_pred = (const float*)d_in[6];
  const int* st = (const int*)d_in[7];
  const int* dt = (const int*)d_in[8];
  const int* etc = (const int*)d_in[9];
  const int* em = (const int*)d_in[10];
  int E = in_sizes[7];

  cudaFuncSetAttribute(main_kernel, cudaFuncAttributeMaxDynamicSharedMemorySize,
                       (int)sizeof(SmemT));
  prep_kernel<<<512, 256>>>(W1, W2, W_pred);
  int grid = (E + TM - 1) / TM;
  main_kernel<<<grid, THREADS, sizeof(SmemT)>>>(h_src, h_dst, b_dec, b_pred, st, dt, etc, em,
                                                (float*)d_out, E);
}

// round 16
// speedup vs baseline: 1.0134x; 1.0134x over previous
#include <cuda_runtime.h>
#include <cuda_bf16.h>
#include <stdint.h>

#define TM 128
#define THREADS 512
#define APAD 40
#define BPAD 40
#define HP 264

// device scratch
__device__ __align__(16) __nv_bfloat16 g_Wt[256 * 512];   // [n][k] decoder weights, bf16
__device__ __align__(16) __nv_bfloat16 g_Wp2[256 * 256];  // [p*16+c][k] head weights, bf16
__device__ float g_sums[16];
__device__ float g_cnts[16];
__device__ int g_done;

struct SmemT {
  __nv_bfloat16 As[2][128 * APAD];
  __nv_bfloat16 Bs[2][256 * BPAD];
  __nv_bfloat16 h[128 * HP];
  float Lg[128 * 17];
  float bias[256];
  float bpred[256];
  int em[16 * 24];
  int spair[128];
  int slabel[128];
  float psum[16];
  int cnt[16];
  int offp[16];
  int cur[16];
  int bucket[128];
};

__global__ void prep_kernel(const float* __restrict__ W1, const float* __restrict__ W2,
                            const float* __restrict__ Wp) {
  int i = blockIdx.x * blockDim.x + threadIdx.x;
  if (i < 256 * 512) {
    int n = i >> 9, k = i & 511;
    float v = (k < 256) ? W1[k * 256 + n] : W2[(k - 256) * 256 + n];
    g_Wt[n * 512 + k] = __float2bfloat16(v);
  }
  if (i < 256 * 256) {
    int col = i >> 8, k = i & 255;
    int p = col >> 4, c = col & 15;
    g_Wp2[col * 256 + k] = __float2bfloat16(Wp[p * 4096 + k * 16 + c]);
  }
  if (i < 16) { g_sums[i] = 0.f; g_cnts[i] = 0.f; }
  if (i == 0) g_done = 0;
}

__device__ __forceinline__ void mma16816(float* c, uint32_t a0, uint32_t a1, uint32_t a2,
                                         uint32_t a3, uint32_t b0, uint32_t b1) {
  asm volatile(
      "mma.sync.aligned.m16n8k16.row.col.f32.bf16.bf16.f32 "
      "{%0,%1,%2,%3}, {%4,%5,%6,%7}, {%8,%9}, {%0,%1,%2,%3};\n"
      : "+f"(c[0]), "+f"(c[1]), "+f"(c[2]), "+f"(c[3])
      : "r"(a0), "r"(a1), "r"(a2), "r"(a3), "r"(b0), "r"(b1));
}

__device__ __forceinline__ void ldsm4(uint32_t& r0, uint32_t& r1, uint32_t& r2, uint32_t& r3,
                                      uint32_t a) {
  asm volatile("ldmatrix.sync.aligned.m8n8.x4.shared.b16 {%0,%1,%2,%3}, [%4];"
               : "=r"(r0), "=r"(r1), "=r"(r2), "=r"(r3)
               : "r"(a));
}

__device__ __forceinline__ uint32_t s2u(const void* p) {
  uint32_t a;
  asm("{ .reg .u64 t; cvta.to.shared.u64 t, %1; cvt.u32.u64 %0, t; }" : "=r"(a) : "l"(p));
  return a;
}

__device__ __forceinline__ uint4 pack8(float4 a, float4 b) {
  __nv_bfloat162 p0 = __floats2bfloat162_rn(a.x, a.y);
  __nv_bfloat162 p1 = __floats2bfloat162_rn(a.z, a.w);
  __nv_bfloat162 p2 = __floats2bfloat162_rn(b.x, b.y);
  __nv_bfloat162 p3 = __floats2bfloat162_rn(b.z, b.w);
  uint4 u;
  u.x = *(uint32_t*)&p0; u.y = *(uint32_t*)&p1;
  u.z = *(uint32_t*)&p2; u.w = *(uint32_t*)&p3;
  return u;
}

__global__ __launch_bounds__(THREADS, 1)
void main_kernel(const float* __restrict__ h_src, const float* __restrict__ h_dst,
                 const float* __restrict__ b_dec, const float* __restrict__ b_pred,
                 const int* __restrict__ st, const int* __restrict__ dt,
                 const int* __restrict__ etc, const int* __restrict__ emap,
                 float* __restrict__ out, int E) {
  extern __shared__ __align__(16) char smem_raw[];
  SmemT* S = (SmemT*)smem_raw;
  const int tid = threadIdx.x;
  const int warp = tid >> 5, lane = tid & 31;
  const int wm = warp & 3, wn = warp >> 2;
  const long e0 = (long)blockIdx.x * TM;
  const int kq = (lane & 3) * 2;
  const int rb = lane >> 2;
  const uint32_t su = s2u(smem_raw);
  const int nvalid = (int)((E - e0) < TM ? (E - e0) : TM);
  // per-lane ldmatrix fragment offset (bytes): row (lane&15), k-half (lane&16)
  const uint32_t fro = (uint32_t)(((lane & 15) * APAD + ((lane >> 4) & 1) * 8) * 2);

  for (int i = tid; i < 256; i += THREADS) { S->bias[i] = b_dec[i]; S->bpred[i] = b_pred[i]; }
  for (int i = tid; i < 384; i += THREADS) S->em[i] = emap[i];
  if (tid < 16) { S->psum[tid] = 0.f; S->cnt[tid] = 0; }
  __syncthreads();
  if (tid < 128) {
    long e = e0 + tid; if (e >= E) e = E - 1;
    int p = st[e] * 4 + dt[e];
    S->spair[tid] = p;
    S->slabel[tid] = S->em[p * 24 + etc[e]];
    if (tid < nvalid) atomicAdd(&S->cnt[p], 1);
  }
  __syncthreads();
  if (tid == 0) {
    int a = 0;
#pragma unroll
    for (int p = 0; p < 16; ++p) { S->offp[p] = a; S->cur[p] = a; a += S->cnt[p]; }
  }
  __syncthreads();
  if (tid < nvalid) {
    int pos = atomicAdd(&S->cur[S->spair[tid]], 1);
    S->bucket[pos] = tid;
  }

  // ---- GEMM1: h = relu([h_src|h_dst] @ Wt^T + b), KC=32 double-buffered ----
  float acc[2][8][4];
#pragma unroll
  for (int a = 0; a < 2; a++)
#pragma unroll
    for (int b = 0; b < 8; b++)
#pragma unroll
      for (int c = 0; c < 4; c++) acc[a][b][c] = 0.f;

  const int ar = tid >> 2, ac = (tid & 3) * 8;
  long ae = e0 + ar; if (ae >= E) ae = E - 1;
  const int bn = tid >> 1, bh = (tid & 1) * 16;

  const float* apA = h_src + ae * 256;
  float4 av0 = *(const float4*)(apA + ac);
  float4 av1 = *(const float4*)(apA + ac + 4);
  uint4 bv0 = *(const uint4*)(g_Wt + bn * 512 + bh);
  uint4 bv1 = *(const uint4*)(g_Wt + bn * 512 + bh + 8);

  *(uint4*)(&S->As[0][ar * APAD + ac]) = pack8(av0, av1);
  *(uint4*)(&S->Bs[0][bn * BPAD + bh]) = bv0;
  *(uint4*)(&S->Bs[0][bn * BPAD + bh + 8]) = bv1;
  __syncthreads();

  const uint32_t A0u = su + (uint32_t)((char*)&S->As[0][0] - smem_raw);
  const uint32_t A1u = su + (uint32_t)((char*)&S->As[1][0] - smem_raw);
  const uint32_t B0u = su + (uint32_t)((char*)&S->Bs[0][0] - smem_raw);
  const uint32_t B1u = su + (uint32_t)((char*)&S->Bs[1][0] - smem_raw);

  for (int it = 0; it < 16; ++it) {
    const int cur = it & 1;
    const bool more = (it + 1 < 16);
    if (more) {
      int kb = (it + 1) * 32;
      const float* ap = (kb < 256) ? (h_src + ae * 256 + kb) : (h_dst + ae * 256 + (kb - 256));
      av0 = *(const float4*)(ap + ac);
      av1 = *(const float4*)(ap + ac + 4);
      bv0 = *(const uint4*)(g_Wt + bn * 512 + kb + bh);
      bv1 = *(const uint4*)(g_Wt + bn * 512 + kb + bh + 8);
    }
    const uint32_t Au = (cur ? A1u : A0u);
    const uint32_t Bu = (cur ? B1u : B0u);
#pragma unroll
    for (int ks = 0; ks < 2; ++ks) {
      const int kk = ks * 16;
      uint32_t af[2][4], bf[4][4];
      ldsm4(af[0][0], af[0][1], af[0][2], af[0][3],
            Au + (uint32_t)(((wm * 32) * APAD + kk) * 2) + fro);
      ldsm4(af[1][0], af[1][1], af[1][2], af[1][3],
            Au + (uint32_t)(((wm * 32 + 16) * APAD + kk) * 2) + fro);
      ldsm4(bf[0][0], bf[0][1], bf[0][2], bf[0][3],
            Bu + (uint32_t)(((wn * 64) * BPAD + kk) * 2) + fro);
      ldsm4(bf[1][0], bf[1][1], bf[1][2], bf[1][3],
            Bu + (uint32_t)(((wn * 64 + 16) * BPAD + kk) * 2) + fro);
      mma16816(acc[0][0], af[0][0], af[0][1], af[0][2], af[0][3], bf[0][0], bf[0][2]);
      mma16816(acc[1][0], af[1][0], af[1][1], af[1][2], af[1][3], bf[0][0], bf[0][2]);
      mma16816(acc[0][1], af[0][0], af[0][1], af[0][2], af[0][3], bf[0][1], bf[0][3]);
      mma16816(acc[1][1], af[1][0], af[1][1], af[1][2], af[1][3], bf[0][1], bf[0][3]);
      ldsm4(bf[2][0], bf[2][1], bf[2][2], bf[2][3],
            Bu + (uint32_t)(((wn * 64 + 32) * BPAD + kk) * 2) + fro);
      mma16816(acc[0][2], af[0][0], af[0][1], af[0][2], af[0][3], bf[1][0], bf[1][2]);
      mma16816(acc[1][2], af[1][0], af[1][1], af[1][2], af[1][3], bf[1][0], bf[1][2]);
      mma16816(acc[0][3], af[0][0], af[0][1], af[0][2], af[0][3], bf[1][1], bf[1][3]);
      mma16816(acc[1][3], af[1][0], af[1][1], af[1][2], af[1][3], bf[1][1], bf[1][3]);
      ldsm4(bf[3][0], bf[3][1], bf[3][2], bf[3][3],
            Bu + (uint32_t)(((wn * 64 + 48) * BPAD + kk) * 2) + fro);
      mma16816(acc[0][4], af[0][0], af[0][1], af[0][2], af[0][3], bf[2][0], bf[2][2]);
      mma16816(acc[1][4], af[1][0], af[1][1], af[1][2], af[1][3], bf[2][0], bf[2][2]);
      mma16816(acc[0][5], af[0][0], af[0][1], af[0][2], af[0][3], bf[2][1], bf[2][3]);
      mma16816(acc[1][5], af[1][0], af[1][1], af[1][2], af[1][3], bf[2][1], bf[2][3]);
      mma16816(acc[0][6], af[0][0], af[0][1], af[0][2], af[0][3], bf[3][0], bf[3][2]);
      mma16816(acc[1][6], af[1][0], af[1][1], af[1][2], af[1][3], bf[3][0], bf[3][2]);
      mma16816(acc[0][7], af[0][0], af[0][1], af[0][2], af[0][3], bf[3][1], bf[3][3]);
      mma16816(acc[1][7], af[1][0], af[1][1], af[1][2], af[1][3], bf[3][1], bf[3][3]);
    }
    if (more) {
      *(uint4*)(&S->As[cur ^ 1][ar * APAD + ac]) = pack8(av0, av1);
      *(uint4*)(&S->Bs[cur ^ 1][bn * BPAD + bh]) = bv0;
      *(uint4*)(&S->Bs[cur ^ 1][bn * BPAD + bh + 8]) = bv1;
    }
    __syncthreads();
  }

  // epilogue: bias + relu -> h (bf16 in smem)
  char* Hb = (char*)S->h;
#pragma unroll
  for (int mi = 0; mi < 2; ++mi) {
    int r = wm * 32 + mi * 16 + rb;
#pragma unroll
    for (int ni = 0; ni < 8; ++ni) {
      int n0 = wn * 64 + ni * 8 + (lane & 3) * 2;
      float bb0 = S->bias[n0], bb1 = S->bias[n0 + 1];
      __nv_bfloat162 q0 = __floats2bfloat162_rn(fmaxf(acc[mi][ni][0] + bb0, 0.f),
                                                fmaxf(acc[mi][ni][1] + bb1, 0.f));
      __nv_bfloat162 q1 = __floats2bfloat162_rn(fmaxf(acc[mi][ni][2] + bb0, 0.f),
                                                fmaxf(acc[mi][ni][3] + bb1, 0.f));
      *(uint32_t*)(Hb + (r * HP + n0) * 2) = *(uint32_t*)&q0;
      *(uint32_t*)(Hb + ((r + 8) * HP + n0) * 2) = *(uint32_t*)&q1;
    }
  }
  __syncthreads();

  // ---- GEMM2 (bucketed): warp w handles pair w; only the selected head ----
  {
    const int p = warp;
    const int m = S->cnt[p];
    const int off = S->offp[p];
    const __nv_bfloat16* Hh = S->h;
    const __nv_bfloat16* Wb = g_Wp2 + (p * 16) * 256;  // 16 cols x 256 k, L2-hot
    for (int t = 0; t * 16 < m; ++t) {
      int i0 = t * 16 + rb, i1 = i0 + 8;
      int r0 = (i0 < m) ? S->bucket[off + i0] : S->bucket[off];
      int r1 = (i1 < m) ? S->bucket[off + i1] : S->bucket[off];
      float a0[4] = {0.f, 0.f, 0.f, 0.f};
      float a1[4] = {0.f, 0.f, 0.f, 0.f};
#pragma unroll 4
      for (int ks = 0; ks < 16; ++ks) {
        int kk = ks * 16 + kq;
        uint32_t f0 = *(const uint32_t*)(Hh + r0 * HP + kk);
        uint32_t f1 = *(const uint32_t*)(Hh + r1 * HP + kk);
        uint32_t f2 = *(const uint32_t*)(Hh + r0 * HP + kk + 8);
        uint32_t f3 = *(const uint32_t*)(Hh + r1 * HP + kk + 8);
        uint32_t b0 = *(const uint32_t*)(Wb + rb * 256 + kk);
        uint32_t b1 = *(const uint32_t*)(Wb + rb * 256 + kk + 8);
        uint32_t b2 = *(const uint32_t*)(Wb + (8 + rb) * 256 + kk);
        uint32_t b3 = *(const uint32_t*)(Wb + (8 + rb) * 256 + kk + 8);
        mma16816(a0, f0, f1, f2, f3, b0, b1);
        mma16816(a1, f0, f1, f2, f3, b2, b3);
      }
      int c0 = (lane & 3) * 2;
      if (i0 < m) {
        S->Lg[r0 * 17 + c0] = a0[0];
        S->Lg[r0 * 17 + c0 + 1] = a0[1];
        S->Lg[r0 * 17 + 8 + c0] = a1[0];
        S->Lg[r0 * 17 + 8 + c0 + 1] = a1[1];
      }
      if (i1 < m) {
        S->Lg[r1 * 17 + c0] = a0[2];
        S->Lg[r1 * 17 + c0 + 1] = a0[3];
        S->Lg[r1 * 17 + 8 + c0] = a1[2];
        S->Lg[r1 * 17 + 8 + c0 + 1] = a1[3];
      }
    }
  }
  __syncthreads();

  // per-edge softmax NLL + per-pair partials
  if (tid < nvalid) {
    const float* L = S->Lg + tid * 17;
    const float* bp = S->bpred + S->spair[tid] * 16;
    float mx = -1e30f;
    float Lb[16];
#pragma unroll
    for (int c = 0; c < 16; ++c) { Lb[c] = L[c] + bp[c]; mx = fmaxf(mx, Lb[c]); }
    float s = 0.f;
#pragma unroll
    for (int c = 0; c < 16; ++c) s += __expf(Lb[c] - mx);
    float l = __logf(s) + mx - Lb[S->slabel[tid]];
    atomicAdd(&S->psum[S->spair[tid]], l);
  }
  __syncthreads();
  if (tid < 16 && S->cnt[tid] > 0) {
    atomicAdd(&g_sums[tid], S->psum[tid]);
    atomicAdd(&g_cnts[tid], (float)S->cnt[tid]);
  }
  __threadfence();
  __syncthreads();
  if (tid == 0) {
    int prev = atomicAdd(&g_done, 1);
    if (prev == (int)gridDim.x - 1) {
      __threadfence();
      float ls = 0.f, np = 0.f;
#pragma unroll
      for (int p = 0; p < 16; ++p) {
        float c = g_cnts[p];
        if (c > 0.f) { ls += g_sums[p] / c; np += 1.f; }
      }
      out[0] = ls / np;
    }
  }
}

extern "C" void kernel_launch(void* const* d_in, const int* in_sizes, int n_in,
                              void* d_out, int out_size) {
  const float* h_src = (const float*)d_in[0];
  const float* h_dst = (const float*)d_in[1];
  const float* W1 = (const float*)d_in[2];
  const float* W2 = (const float*)d_in[3];
  const float* b_dec = (const float*)d_in[4];
  const float* W_pred = (const float*)d_in[5];
  const float* b_pred = (const float*)d_in[6];
  const int* st = (const int*)d_in[7];
  const int* dt = (const int*)d_in[8];
  const int* etc = (const int*)d_in[9];
  const int* em = (const int*)d_in[10];
  int E = in_sizes[7];

  cudaFuncSetAttribute(main_kernel, cudaFuncAttributeMaxDynamicSharedMemorySize,
                       (int)sizeof(SmemT));
  prep_kernel<<<512, 256>>>(W1, W2, W_pred);
  int grid = (E + TM - 1) / TM;
  main_kernel<<<grid, THREADS, sizeof(SmemT)>>>(h_src, h_dst, b_dec, b_pred, st, dt, etc, em,
                                                (float*)d_out, E);
}

// round 17
// speedup vs baseline: 1.0259x; 1.0123x over previous
#include <cuda_runtime.h>
#include <cuda_bf16.h>
#include <stdint.h>

#define TM 128
#define THREADS 512
#define APAD 40
#define BPAD 40
#define HP 264

// device scratch
__device__ __align__(16) __nv_bfloat16 g_Wt[256 * 512];   // [n][k] decoder weights, bf16
__device__ __align__(16) __nv_bfloat16 g_Wp2[256 * 256];  // [p*16+c][k] head weights, bf16
__device__ float g_sums[16];
__device__ float g_cnts[16];
__device__ int g_done;

struct SmemT {
  __nv_bfloat16 As[2][128 * APAD];
  __nv_bfloat16 Bs[2][256 * BPAD];
  __nv_bfloat16 h[128 * HP];
  float Lg[128 * 17];
  float bias[256];
  float bpred[256];
  int em[16 * 24];
  int spair[128];
  int slabel[128];
  float psum[16];
  int pcnt[16];
  int cnt[16];
  int offp[16];
  int cur[16];
  int bucket[128];
};

__global__ void prep_kernel(const float* __restrict__ W1, const float* __restrict__ W2,
                            const float* __restrict__ Wp) {
  int i = blockIdx.x * blockDim.x + threadIdx.x;
  if (i < 256 * 512) {
    int n = i >> 9, k = i & 511;
    float v = (k < 256) ? W1[k * 256 + n] : W2[(k - 256) * 256 + n];
    g_Wt[n * 512 + k] = __float2bfloat16(v);
  }
  if (i < 256 * 256) {
    int col = i >> 8, k = i & 255;
    int p = col >> 4, c = col & 15;
    g_Wp2[col * 256 + k] = __float2bfloat16(Wp[p * 4096 + k * 16 + c]);
  }
  if (i < 16) { g_sums[i] = 0.f; g_cnts[i] = 0.f; }
  if (i == 0) g_done = 0;
}

__device__ __forceinline__ void mma16816(float* c, uint32_t a0, uint32_t a1, uint32_t a2,
                                         uint32_t a3, uint32_t b0, uint32_t b1) {
  asm volatile(
      "mma.sync.aligned.m16n8k16.row.col.f32.bf16.bf16.f32 "
      "{%0,%1,%2,%3}, {%4,%5,%6,%7}, {%8,%9}, {%0,%1,%2,%3};\n"
      : "+f"(c[0]), "+f"(c[1]), "+f"(c[2]), "+f"(c[3])
      : "r"(a0), "r"(a1), "r"(a2), "r"(a3), "r"(b0), "r"(b1));
}

__device__ __forceinline__ void ldsm4(uint32_t& r0, uint32_t& r1, uint32_t& r2, uint32_t& r3,
                                      uint32_t a) {
  asm volatile("ldmatrix.sync.aligned.m8n8.x4.shared.b16 {%0,%1,%2,%3}, [%4];"
               : "=r"(r0), "=r"(r1), "=r"(r2), "=r"(r3)
               : "r"(a));
}

__device__ __forceinline__ uint32_t s2u(const void* p) {
  uint32_t a;
  asm("{ .reg .u64 t; cvta.to.shared.u64 t, %1; cvt.u32.u64 %0, t; }" : "=r"(a) : "l"(p));
  return a;
}

__device__ __forceinline__ uint4 pack8(float4 a, float4 b) {
  __nv_bfloat162 p0 = __floats2bfloat162_rn(a.x, a.y);
  __nv_bfloat162 p1 = __floats2bfloat162_rn(a.z, a.w);
  __nv_bfloat162 p2 = __floats2bfloat162_rn(b.x, b.y);
  __nv_bfloat162 p3 = __floats2bfloat162_rn(b.z, b.w);
  uint4 u;
  u.x = *(uint32_t*)&p0; u.y = *(uint32_t*)&p1;
  u.z = *(uint32_t*)&p2; u.w = *(uint32_t*)&p3;
  return u;
}

__global__ __launch_bounds__(THREADS, 1)
void main_kernel(const float* __restrict__ h_src, const float* __restrict__ h_dst,
                 const float* __restrict__ b_dec, const float* __restrict__ b_pred,
                 const int* __restrict__ st, const int* __restrict__ dt,
                 const int* __restrict__ etc, const int* __restrict__ emap,
                 float* __restrict__ out, int E) {
  extern __shared__ __align__(16) char smem_raw[];
  SmemT* S = (SmemT*)smem_raw;
  const int tid = threadIdx.x;
  const int warp = tid >> 5, lane = tid & 31;
  const int wm = warp & 3, wn = warp >> 2;
  const long e0 = (long)blockIdx.x * TM;
  const int kq = (lane & 3) * 2;
  const int rb = lane >> 2;
  const uint32_t su = s2u(smem_raw);
  // per-lane ldmatrix fragment offset (bytes): row (lane&15), k-half (lane&16)
  const uint32_t fro = (uint32_t)(((lane & 15) * APAD + ((lane >> 4) & 1) * 8) * 2);

  for (int i = tid; i < 256; i += THREADS) { S->bias[i] = b_dec[i]; S->bpred[i] = b_pred[i]; }
  for (int i = tid; i < 384; i += THREADS) S->em[i] = emap[i];
  if (tid < 16) { S->psum[tid] = 0.f; S->pcnt[tid] = 0; S->cnt[tid] = 0; }
  __syncthreads();
  if (tid < 128) {
    long e = e0 + tid; if (e >= E) e = E - 1;
    int p = st[e] * 4 + dt[e];
    S->spair[tid] = p;
    S->slabel[tid] = S->em[p * 24 + etc[e]];
    atomicAdd(&S->cnt[p], 1);
  }
  __syncthreads();
  if (tid == 0) {
    int a = 0;
#pragma unroll
    for (int p = 0; p < 16; ++p) { S->offp[p] = a; S->cur[p] = a; a += S->cnt[p]; }
  }
  __syncthreads();
  if (tid < 128) {
    int pos = atomicAdd(&S->cur[S->spair[tid]], 1);
    S->bucket[pos] = tid;
  }

  // ---- GEMM1: h = relu([h_src|h_dst] @ Wt^T + b), KC=32 double-buffered ----
  float acc[2][8][4];
#pragma unroll
  for (int a = 0; a < 2; a++)
#pragma unroll
    for (int b = 0; b < 8; b++)
#pragma unroll
      for (int c = 0; c < 4; c++) acc[a][b][c] = 0.f;

  const int ar = tid >> 2, ac = (tid & 3) * 8;
  long ae = e0 + ar; if (ae >= E) ae = E - 1;
  const int bn = tid >> 1, bh = (tid & 1) * 16;

  const float* apA = h_src + ae * 256;
  float4 av0 = *(const float4*)(apA + ac);
  float4 av1 = *(const float4*)(apA + ac + 4);
  uint4 bv0 = *(const uint4*)(g_Wt + bn * 512 + bh);
  uint4 bv1 = *(const uint4*)(g_Wt + bn * 512 + bh + 8);

  *(uint4*)(&S->As[0][ar * APAD + ac]) = pack8(av0, av1);
  *(uint4*)(&S->Bs[0][bn * BPAD + bh]) = bv0;
  *(uint4*)(&S->Bs[0][bn * BPAD + bh + 8]) = bv1;
  __syncthreads();

  const uint32_t A0u = su + (uint32_t)((char*)&S->As[0][0] - smem_raw);
  const uint32_t A1u = su + (uint32_t)((char*)&S->As[1][0] - smem_raw);
  const uint32_t B0u = su + (uint32_t)((char*)&S->Bs[0][0] - smem_raw);
  const uint32_t B1u = su + (uint32_t)((char*)&S->Bs[1][0] - smem_raw);

  for (int it = 0; it < 16; ++it) {
    const int cur = it & 1;
    const bool more = (it + 1 < 16);
    if (more) {
      int kb = (it + 1) * 32;
      const float* ap = (kb < 256) ? (h_src + ae * 256 + kb) : (h_dst + ae * 256 + (kb - 256));
      av0 = *(const float4*)(ap + ac);
      av1 = *(const float4*)(ap + ac + 4);
      bv0 = *(const uint4*)(g_Wt + bn * 512 + kb + bh);
      bv1 = *(const uint4*)(g_Wt + bn * 512 + kb + bh + 8);
    }
    const uint32_t Au = (cur ? A1u : A0u);
    const uint32_t Bu = (cur ? B1u : B0u);
#pragma unroll
    for (int ks = 0; ks < 2; ++ks) {
      const int kk = ks * 16;
      uint32_t af[2][4], bf[4][4];
      ldsm4(af[0][0], af[0][1], af[0][2], af[0][3],
            Au + (uint32_t)(((wm * 32) * APAD + kk) * 2) + fro);
      ldsm4(af[1][0], af[1][1], af[1][2], af[1][3],
            Au + (uint32_t)(((wm * 32 + 16) * APAD + kk) * 2) + fro);
      ldsm4(bf[0][0], bf[0][1], bf[0][2], bf[0][3],
            Bu + (uint32_t)(((wn * 64) * BPAD + kk) * 2) + fro);
      ldsm4(bf[1][0], bf[1][1], bf[1][2], bf[1][3],
            Bu + (uint32_t)(((wn * 64 + 16) * BPAD + kk) * 2) + fro);
      mma16816(acc[0][0], af[0][0], af[0][1], af[0][2], af[0][3], bf[0][0], bf[0][2]);
      mma16816(acc[1][0], af[1][0], af[1][1], af[1][2], af[1][3], bf[0][0], bf[0][2]);
      mma16816(acc[0][1], af[0][0], af[0][1], af[0][2], af[0][3], bf[0][1], bf[0][3]);
      mma16816(acc[1][1], af[1][0], af[1][1], af[1][2], af[1][3], bf[0][1], bf[0][3]);
      ldsm4(bf[2][0], bf[2][1], bf[2][2], bf[2][3],
            Bu + (uint32_t)(((wn * 64 + 32) * BPAD + kk) * 2) + fro);
      mma16816(acc[0][2], af[0][0], af[0][1], af[0][2], af[0][3], bf[1][0], bf[1][2]);
      mma16816(acc[1][2], af[1][0], af[1][1], af[1][2], af[1][3], bf[1][0], bf[1][2]);
      mma16816(acc[0][3], af[0][0], af[0][1], af[0][2], af[0][3], bf[1][1], bf[1][3]);
      mma16816(acc[1][3], af[1][0], af[1][1], af[1][2], af[1][3], bf[1][1], bf[1][3]);
      ldsm4(bf[3][0], bf[3][1], bf[3][2], bf[3][3],
            Bu + (uint32_t)(((wn * 64 + 48) * BPAD + kk) * 2) + fro);
      mma16816(acc[0][4], af[0][0], af[0][1], af[0][2], af[0][3], bf[2][0], bf[2][2]);
      mma16816(acc[1][4], af[1][0], af[1][1], af[1][2], af[1][3], bf[2][0], bf[2][2]);
      mma16816(acc[0][5], af[0][0], af[0][1], af[0][2], af[0][3], bf[2][1], bf[2][3]);
      mma16816(acc[1][5], af[1][0], af[1][1], af[1][2], af[1][3], bf[2][1], bf[2][3]);
      mma16816(acc[0][6], af[0][0], af[0][1], af[0][2], af[0][3], bf[3][0], bf[3][2]);
      mma16816(acc[1][6], af[1][0], af[1][1], af[1][2], af[1][3], bf[3][0], bf[3][2]);
      mma16816(acc[0][7], af[0][0], af[0][1], af[0][2], af[0][3], bf[3][1], bf[3][3]);
      mma16816(acc[1][7], af[1][0], af[1][1], af[1][2], af[1][3], bf[3][1], bf[3][3]);
    }
    if (more) {
      *(uint4*)(&S->As[cur ^ 1][ar * APAD + ac]) = pack8(av0, av1);
      *(uint4*)(&S->Bs[cur ^ 1][bn * BPAD + bh]) = bv0;
      *(uint4*)(&S->Bs[cur ^ 1][bn * BPAD + bh + 8]) = bv1;
    }
    __syncthreads();
  }

  // epilogue: bias + relu -> h (bf16 in smem)
  char* Hb = (char*)S->h;
#pragma unroll
  for (int mi = 0; mi < 2; ++mi) {
    int r = wm * 32 + mi * 16 + rb;
#pragma unroll
    for (int ni = 0; ni < 8; ++ni) {
      int n0 = wn * 64 + ni * 8 + (lane & 3) * 2;
      float bb0 = S->bias[n0], bb1 = S->bias[n0 + 1];
      __nv_bfloat162 q0 = __floats2bfloat162_rn(fmaxf(acc[mi][ni][0] + bb0, 0.f),
                                                fmaxf(acc[mi][ni][1] + bb1, 0.f));
      __nv_bfloat162 q1 = __floats2bfloat162_rn(fmaxf(acc[mi][ni][2] + bb0, 0.f),
                                                fmaxf(acc[mi][ni][3] + bb1, 0.f));
      *(uint32_t*)(Hb + (r * HP + n0) * 2) = *(uint32_t*)&q0;
      *(uint32_t*)(Hb + ((r + 8) * HP + n0) * 2) = *(uint32_t*)&q1;
    }
  }
  __syncthreads();

  // ---- GEMM2 (bucketed): warp w handles pair w; only the selected head ----
  {
    const int p = warp;
    const int m = S->cnt[p];
    const int off = S->offp[p];
    const __nv_bfloat16* Hh = S->h;
    const __nv_bfloat16* Wb = g_Wp2 + (p * 16) * 256;  // 16 cols x 256 k, L2-hot
    for (int t = 0; t * 16 < m; ++t) {
      int i0 = t * 16 + rb, i1 = i0 + 8;
      int r0 = (i0 < m) ? S->bucket[off + i0] : S->bucket[off];
      int r1 = (i1 < m) ? S->bucket[off + i1] : S->bucket[off];
      float a0[4] = {0.f, 0.f, 0.f, 0.f};
      float a1[4] = {0.f, 0.f, 0.f, 0.f};
#pragma unroll 4
      for (int ks = 0; ks < 16; ++ks) {
        int kk = ks * 16 + kq;
        uint32_t f0 = *(const uint32_t*)(Hh + r0 * HP + kk);
        uint32_t f1 = *(const uint32_t*)(Hh + r1 * HP + kk);
        uint32_t f2 = *(const uint32_t*)(Hh + r0 * HP + kk + 8);
        uint32_t f3 = *(const uint32_t*)(Hh + r1 * HP + kk + 8);
        uint32_t b0 = *(const uint32_t*)(Wb + rb * 256 + kk);
        uint32_t b1 = *(const uint32_t*)(Wb + rb * 256 + kk + 8);
        uint32_t b2 = *(const uint32_t*)(Wb + (8 + rb) * 256 + kk);
        uint32_t b3 = *(const uint32_t*)(Wb + (8 + rb) * 256 + kk + 8);
        mma16816(a0, f0, f1, f2, f3, b0, b1);
        mma16816(a1, f0, f1, f2, f3, b2, b3);
      }
      int c0 = (lane & 3) * 2;
      if (i0 < m) {
        S->Lg[r0 * 17 + c0] = a0[0];
        S->Lg[r0 * 17 + c0 + 1] = a0[1];
        S->Lg[r0 * 17 + 8 + c0] = a1[0];
        S->Lg[r0 * 17 + 8 + c0 + 1] = a1[1];
      }
      if (i1 < m) {
        S->Lg[r1 * 17 + c0] = a0[2];
        S->Lg[r1 * 17 + c0 + 1] = a0[3];
        S->Lg[r1 * 17 + 8 + c0] = a1[2];
        S->Lg[r1 * 17 + 8 + c0 + 1] = a1[3];
      }
    }
  }
  __syncthreads();

  // per-edge softmax NLL + per-pair partials
  if (tid < 128) {
    long e = e0 + tid;
    if (e < E) {
      const float* L = S->Lg + tid * 17;
      const float* bp = S->bpred + S->spair[tid] * 16;
      float mx = -1e30f;
      float Lb[16];
#pragma unroll
      for (int c = 0; c < 16; ++c) { Lb[c] = L[c] + bp[c]; mx = fmaxf(mx, Lb[c]); }
      float s = 0.f;
#pragma unroll
      for (int c = 0; c < 16; ++c) s += __expf(Lb[c] - mx);
      float l = __logf(s) + mx - Lb[S->slabel[tid]];
      atomicAdd(&S->psum[S->spair[tid]], l);
      atomicAdd(&S->pcnt[S->spair[tid]], 1);
    }
  }
  __syncthreads();
  if (tid < 16 && S->pcnt[tid] > 0) {
    atomicAdd(&g_sums[tid], S->psum[tid]);
    atomicAdd(&g_cnts[tid], (float)S->pcnt[tid]);
  }
  __threadfence();
  __syncthreads();
  if (tid == 0) {
    int prev = atomicAdd(&g_done, 1);
    if (prev == (int)gridDim.x - 1) {
      __threadfence();
      float ls = 0.f, np = 0.f;
#pragma unroll
      for (int p = 0; p < 16; ++p) {
        float c = g_cnts[p];
        if (c > 0.f) { ls += g_sums[p] / c; np += 1.f; }
      }
      out[0] = ls / np;
    }
  }
}

extern "C" void kernel_launch(void* const* d_in, const int* in_sizes, int n_in,
                              void* d_out, int out_size) {
  const float* h_src = (const float*)d_in[0];
  const float* h_dst = (const float*)d_in[1];
  const float* W1 = (const float*)d_in[2];
  const float* W2 = (const float*)d_in[3];
  const float* b_dec = (const float*)d_in[4];
  const float* W_pred = (const float*)d_in[5];
  const float* b_pred = (const float*)d_in[6];
  const int* st = (const int*)d_in[7];
  const int* dt = (const int*)d_in[8];
  const int* etc = (const int*)d_in[9];
  const int* em = (const int*)d_in[10];
  int E = in_sizes[7];

  cudaFuncSetAttribute(main_kernel, cudaFuncAttributeMaxDynamicSharedMemorySize,
                       (int)sizeof(SmemT));
  prep_kernel<<<512, 256>>>(W1, W2, W_pred);
  int grid = (E + TM - 1) / TM;
  main_kernel<<<grid, THREADS, sizeof(SmemT)>>>(h_src, h_dst, b_dec, b_pred, st, dt, etc, em,
                                                (float*)d_out, E);
}